// round 1
// baseline (speedup 1.0000x reference)
#include <cuda_runtime.h>

#define HW 225
#define ST 226           // 225 positions + 1 guaranteed-zero slot per channel
#define NCH 128
#define TAPSTRIDE (128*128)
#define SMEM_BYTES (2*NCH*ST*4)

// per-direction tap offsets (OFFSETS in the reference):
// d0 horiz, d1 vert, d2 anti-diag, d3 main diag
__constant__ int c_DI0[4] = { 0,-1, 1,-1};
__constant__ int c_DJ0[4] = {-1, 0,-1,-1};
__constant__ int c_DI2[4] = { 0, 1,-1, 1};
__constant__ int c_DJ2[4] = { 1, 0, 1, 1};

// transposed res dconv weights: [i][t][o][c] (c contiguous for LDG.128)
__device__ __align__(16) float g_dwt[4*3*128*128];

__global__ void prep_kernel(const float* __restrict__ w) {
    const int n = 4*3*128*128;
    for (int idx = blockIdx.x*blockDim.x + threadIdx.x; idx < n;
         idx += gridDim.x*blockDim.x) {
        int c = idx & 127;
        int r = idx >> 7;
        int o = r & 127;
        r >>= 7;            // r = i*3 + t
        int t = r % 3;
        int i = r / 3;
        g_dwt[idx] = w[((i*128 + o)*128 + c)*3 + t];
    }
}

__device__ __forceinline__ float silu_f(float x) {
    return x * (1.0f / (1.0f + __expf(-x)));
}

// One fused layer over Cin=128: out[o][p] = (act?)(sum_t sum_c w[t][o][c]*in[c][p+dt]) + bias
// Optionally adds a residual (own element only) and/or writes to global.
template<int NTAPS, bool ACT, bool RESID, bool TOGLOBAL>
__device__ __forceinline__ void layer_c128(
    const float* __restrict__ sin,
    float* sout,                    // smem out (if !TOGLOBAL)
    float* gout,                    // global out base (if TOGLOBAL), rows of 225
    const float* __restrict__ w,    // [NTAPS][Co][128], c contiguous
    const float* __restrict__ bias,
    const float* resid,
    int di0, int dj0, int di2, int dj2)
{
    const int tid = threadIdx.x;
    const int oz    = TOGLOBAL ? (tid >> 5) : (tid >> 4);
    const int pl    = TOGLOBAL ? (tid & 31) : (tid & 15);
    const int lanes = TOGLOBAL ? 32 : 16;
    const int ob = oz * 8;

    float b8[8];
#pragma unroll
    for (int u = 0; u < 8; u++) b8[u] = bias[ob + u];

    const int d0 = di0*15 + dj0;
    const int d2 = di2*15 + dj2;
    const int nchunks = TOGLOBAL ? 2 : 4;

#pragma unroll 1
    for (int ch = 0; ch < nchunks; ch++) {
        int pv[4], pt0[4], pt2[4];
        bool wrv[4];
#pragma unroll
        for (int j = 0; j < 4; j++) {
            int p = pl + lanes*(ch*4 + j);
            bool v = p < HW;
            wrv[j] = v;
            pv[j] = v ? p : HW;        // invalid -> zero slot
            pt0[j] = HW; pt2[j] = HW;
            if (NTAPS == 3) {
                int pi = p / 15, pj = p - pi*15;
                if (v && (unsigned)(pi+di0) < 15u && (unsigned)(pj+dj0) < 15u)
                    pt0[j] = p + d0;
                if (v && (unsigned)(pi+di2) < 15u && (unsigned)(pj+dj2) < 15u)
                    pt2[j] = p + d2;
            }
        }

        float acc[8][4];
#pragma unroll
        for (int u = 0; u < 8; u++)
#pragma unroll
            for (int j = 0; j < 4; j++) acc[u][j] = 0.f;

#pragma unroll
        for (int t = 0; t < NTAPS; t++) {
            const float* wt = w + t*TAPSTRIDE;
            int pcur[4];
#pragma unroll
            for (int j = 0; j < 4; j++)
                pcur[j] = (NTAPS == 3)
                        ? (t == 0 ? pt0[j] : (t == 1 ? pv[j] : pt2[j]))
                        : pv[j];

#pragma unroll 2
            for (int c4 = 0; c4 < 32; c4++) {
                float4 w4[8];
#pragma unroll
                for (int u = 0; u < 8; u++)
                    w4[u] = *reinterpret_cast<const float4*>(wt + (ob+u)*128 + c4*4);
                float vv[4][4];
#pragma unroll
                for (int j = 0; j < 4; j++) {
#pragma unroll
                    for (int cc = 0; cc < 4; cc++)
                        vv[j][cc] = sin[(c4*4 + cc)*ST + pcur[j]];
                }
#pragma unroll
                for (int u = 0; u < 8; u++) {
#pragma unroll
                    for (int j = 0; j < 4; j++) {
                        acc[u][j] = fmaf(w4[u].x, vv[j][0], acc[u][j]);
                        acc[u][j] = fmaf(w4[u].y, vv[j][1], acc[u][j]);
                        acc[u][j] = fmaf(w4[u].z, vv[j][2], acc[u][j]);
                        acc[u][j] = fmaf(w4[u].w, vv[j][3], acc[u][j]);
                    }
                }
            }
        }

#pragma unroll
        for (int u = 0; u < 8; u++) {
#pragma unroll
            for (int j = 0; j < 4; j++) {
                float val = acc[u][j] + b8[u];
                if (ACT)   val = silu_f(val);
                if (RESID) val += resid[(ob+u)*ST + pv[j]];
                if (wrv[j]) {
                    if (TOGLOBAL) gout[(ob+u)*HW + pv[j]] = val;
                    else          sout[(ob+u)*ST + pv[j]] = val;
                }
            }
        }
    }
}

__global__ void __launch_bounds__(256, 1)
mix9s_kernel(const float* __restrict__ x,
             const float* __restrict__ dw0, const float* __restrict__ db0,
             const float* __restrict__ rdb,
             const float* __restrict__ rpw, const float* __restrict__ rpb,
             const float* __restrict__ cw1, const float* __restrict__ cb1,
             const float* __restrict__ cw2, const float* __restrict__ cb2,
             const float* __restrict__ fw,  const float* __restrict__ fb,
             float* __restrict__ out)
{
    extern __shared__ float smem[];
    float* bufA = smem;
    float* bufB = smem + NCH*ST;

    const int tid = threadIdx.x;
    const int b = blockIdx.x & 255;
    const int d = blockIdx.x >> 8;
    const int di0 = c_DI0[d], dj0 = c_DJ0[d], di2 = c_DI2[d], dj2 = c_DJ2[d];

    // init zero slots + stage x (2 channels) into bufB
    if (tid < NCH) { bufA[tid*ST + HW] = 0.f; bufB[tid*ST + HW] = 0.f; }
    const float* xb = x + b*(2*HW);
    for (int idx = tid; idx < 2*HW; idx += 256) {
        int c = idx / HW;
        int p = idx - c*HW;
        bufB[c*ST + p] = xb[idx];
    }
    __syncthreads();

    // ---- dconv0: Cin=2, 3 taps, silu -> bufA ----
    {
        const int oz = tid >> 4, pl = tid & 15;
        const int ob = oz * 8;
        float wr_[8][2][3];
#pragma unroll
        for (int u = 0; u < 8; u++)
#pragma unroll
            for (int c = 0; c < 2; c++)
#pragma unroll
                for (int t = 0; t < 3; t++)
                    wr_[u][c][t] = dw0[((ob+u)*2 + c)*3 + t];
        float b8[8];
#pragma unroll
        for (int u = 0; u < 8; u++) b8[u] = db0[ob+u];

        const int d0 = di0*15 + dj0;
        const int d2 = di2*15 + dj2;
#pragma unroll 1
        for (int ch = 0; ch < 4; ch++) {
            int pv[4], pt0[4], pt2[4];
            bool wrv[4];
#pragma unroll
            for (int j = 0; j < 4; j++) {
                int p = pl + 16*(ch*4 + j);
                bool v = p < HW;
                wrv[j] = v;
                pv[j] = v ? p : HW;
                pt0[j] = HW; pt2[j] = HW;
                int pi = p / 15, pj = p - pi*15;
                if (v && (unsigned)(pi+di0) < 15u && (unsigned)(pj+dj0) < 15u)
                    pt0[j] = p + d0;
                if (v && (unsigned)(pi+di2) < 15u && (unsigned)(pj+dj2) < 15u)
                    pt2[j] = p + d2;
            }
#pragma unroll
            for (int j = 0; j < 4; j++) {
                float v0[2], vc[2], v2[2];
#pragma unroll
                for (int c = 0; c < 2; c++) {
                    v0[c] = bufB[c*ST + pt0[j]];
                    vc[c] = bufB[c*ST + pv[j]];
                    v2[c] = bufB[c*ST + pt2[j]];
                }
#pragma unroll
                for (int u = 0; u < 8; u++) {
                    float a = b8[u];
#pragma unroll
                    for (int c = 0; c < 2; c++) {
                        a = fmaf(wr_[u][c][0], v0[c], a);
                        a = fmaf(wr_[u][c][1], vc[c], a);
                        a = fmaf(wr_[u][c][2], v2[c], a);
                    }
                    a = silu_f(a);
                    if (wrv[j]) bufA[(ob+u)*ST + pv[j]] = a;
                }
            }
        }
    }
    __syncthreads();

    // ---- 4 directional res blocks ----
#pragma unroll 1
    for (int i = 0; i < 4; i++) {
        layer_c128<3, true, false, false>(bufA, bufB, nullptr,
            g_dwt + i*3*TAPSTRIDE, rdb + i*128, nullptr, di0, dj0, di2, dj2);
        __syncthreads();
        layer_c128<1, true, true, false>(bufB, bufA, nullptr,
            rpw + i*TAPSTRIDE, rpb + i*128, bufA, 0, 0, 0, 0);
        __syncthreads();
    }

    // ---- Conv0d res block ----
    layer_c128<1, true, false, false>(bufA, bufB, nullptr, cw1, cb1, nullptr, 0,0,0,0);
    __syncthreads();
    layer_c128<1, true, true, false>(bufB, bufA, nullptr, cw2, cb2, bufA, 0,0,0,0);
    __syncthreads();

    // ---- final 1x1 (128 -> 64), no activation, straight to global ----
    layer_c128<1, false, false, true>(bufA, nullptr, out + (b*4 + d)*64*HW,
                                      fw, fb, nullptr, 0,0,0,0);
}

extern "C" void kernel_launch(void* const* d_in, const int* in_sizes, int n_in,
                              void* d_out, int out_size) {
    (void)in_sizes; (void)n_in; (void)out_size;
    const float* x   = (const float*)d_in[0];
    const float* dw0 = (const float*)d_in[1];
    const float* db0 = (const float*)d_in[2];
    const float* rdw = (const float*)d_in[3];
    const float* rdb = (const float*)d_in[4];
    const float* rpw = (const float*)d_in[5];
    const float* rpb = (const float*)d_in[6];
    const float* cw1 = (const float*)d_in[7];
    const float* cb1 = (const float*)d_in[8];
    const float* cw2 = (const float*)d_in[9];
    const float* cb2 = (const float*)d_in[10];
    const float* fw  = (const float*)d_in[11];
    const float* fb  = (const float*)d_in[12];
    float* out = (float*)d_out;

    cudaFuncSetAttribute(mix9s_kernel,
                         cudaFuncAttributeMaxDynamicSharedMemorySize, SMEM_BYTES);

    prep_kernel<<<768, 256>>>(rdw);
    mix9s_kernel<<<1024, 256, SMEM_BYTES>>>(
        x, dw0, db0, rdb, rpw, rpb, cw1, cb1, cw2, cb2, fw, fb, out);
}